// round 3
// baseline (speedup 1.0000x reference)
#include <cuda_runtime.h>
#include <cstdint>

// Hyperelasticity: closed-form Neo-Hookean stress.
// PK1 = MU*F + (LAM*lnJ - MU)*F^{-T};  PK2 = sym(F^{-1} PK1);  sig = sym(PK1 F^T)/J
//
// Persistent grid-stride kernel, double-buffered cp.async input pipeline,
// smem-transposed fully-coalesced float4 stores.
#define MU   1.0f
#define LAM  1.0f
#define BS   256
#define TILE 256
#define NB4  ((TILE * 9) / 4)   // 576 float4 per tile region

__device__ __forceinline__ uint32_t smem_u32(const void* p) {
    return (uint32_t)__cvta_generic_to_shared(p);
}
__device__ __forceinline__ void cp_async16(uint32_t dst, const void* src) {
    asm volatile("cp.async.cg.shared.global [%0], [%1], 16;\n" :: "r"(dst), "l"(src));
}
__device__ __forceinline__ void cp_commit() { asm volatile("cp.async.commit_group;\n"); }
__device__ __forceinline__ void cp_wait1()  { asm volatile("cp.async.wait_group 1;\n" ::: "memory"); }

__device__ __forceinline__ void compute_point(const float* __restrict__ Fp,
                                              float* __restrict__ o1,
                                              float* __restrict__ o2,
                                              float* __restrict__ o3)
{
    float a = Fp[0], b = Fp[1], c = Fp[2];
    float d = Fp[3], e = Fp[4], f = Fp[5];
    float g = Fp[6], h = Fp[7], i = Fp[8];

    // cofactors: F^{-T} = C/J, F^{-1} = C^T/J
    float C00 = fmaf(e, i, -f * h);
    float C01 = fmaf(f, g, -d * i);
    float C02 = fmaf(d, h, -e * g);
    float C10 = fmaf(c, h, -b * i);
    float C11 = fmaf(a, i, -c * g);
    float C12 = fmaf(b, g, -a * h);
    float C20 = fmaf(b, f, -c * e);
    float C21 = fmaf(c, d, -a * f);
    float C22 = fmaf(a, e, -b * d);

    float J   = a * C00 + b * C01 + c * C02;
    float rJ  = __frcp_rn(J);
    float lnJ = __logf(J);

    float s = (LAM * lnJ - MU) * rJ;
    float P00 = fmaf(s, C00, MU * a);
    float P01 = fmaf(s, C01, MU * b);
    float P02 = fmaf(s, C02, MU * c);
    float P10 = fmaf(s, C10, MU * d);
    float P11 = fmaf(s, C11, MU * e);
    float P12 = fmaf(s, C12, MU * f);
    float P20 = fmaf(s, C20, MU * g);
    float P21 = fmaf(s, C21, MU * h);
    float P22 = fmaf(s, C22, MU * i);

    // Finv = C^T/J
    float I00 = C00 * rJ, I01 = C10 * rJ, I02 = C20 * rJ;
    float I10 = C01 * rJ, I11 = C11 * rJ, I12 = C21 * rJ;
    float I20 = C02 * rJ, I21 = C12 * rJ, I22 = C22 * rJ;

    float M00 = I00*P00 + I01*P10 + I02*P20;
    float M01 = I00*P01 + I01*P11 + I02*P21;
    float M02 = I00*P02 + I01*P12 + I02*P22;
    float M10 = I10*P00 + I11*P10 + I12*P20;
    float M11 = I10*P01 + I11*P11 + I12*P21;
    float M12 = I10*P02 + I11*P12 + I12*P22;
    float M20 = I20*P00 + I21*P10 + I22*P20;
    float M21 = I20*P01 + I21*P11 + I22*P21;
    float M22 = I20*P02 + I21*P12 + I22*P22;

    float S01 = 0.5f * (M01 + M10);
    float S02 = 0.5f * (M02 + M20);
    float S12 = 0.5f * (M12 + M21);

    float T00 = P00*a + P01*b + P02*c;
    float T01 = P00*d + P01*e + P02*f;
    float T02 = P00*g + P01*h + P02*i;
    float T10 = P10*a + P11*b + P12*c;
    float T11 = P10*d + P11*e + P12*f;
    float T12 = P10*g + P11*h + P12*i;
    float T20 = P20*a + P21*b + P22*c;
    float T21 = P20*d + P21*e + P22*f;
    float T22 = P20*g + P21*h + P22*i;

    o1[0] = P00; o1[1] = P01; o1[2] = P02;
    o1[3] = P10; o1[4] = P11; o1[5] = P12;
    o1[6] = P20; o1[7] = P21; o1[8] = P22;

    o2[0] = M00; o2[1] = S01; o2[2] = S02;
    o2[3] = S01; o2[4] = M11; o2[5] = S12;
    o2[6] = S02; o2[7] = S12; o2[8] = M22;

    float G01 = 0.5f * (T01 + T10) * rJ;
    float G02 = 0.5f * (T02 + T20) * rJ;
    float G12 = 0.5f * (T12 + T21) * rJ;
    o3[0] = T00 * rJ; o3[1] = G01;      o3[2] = G02;
    o3[3] = G01;      o3[4] = T11 * rJ; o3[5] = G12;
    o3[6] = G02;      o3[7] = G12;      o3[8] = T22 * rJ;
}

__global__ __launch_bounds__(BS)
void hyper_main(const float* __restrict__ Fin,
                float* __restrict__ out,
                int full_tiles,
                size_t nn)   // nn = (size_t)n * 9
{
    __shared__ __align__(16) float sF[2][TILE * 9];
    __shared__ __align__(16) float sO[TILE * 9];

    const int tid = threadIdx.x;
    const int G   = gridDim.x;

    // prologue: prefetch first tile
    {
        long t0 = blockIdx.x;
        if (t0 < full_tiles) {
            const float4* src = (const float4*)(Fin + (size_t)t0 * TILE * 9);
            float4* dst = (float4*)sF[0];
            #pragma unroll
            for (int i = 0; i < 3; i++) {
                int k = tid + i * BS;
                if (k < NB4) cp_async16(smem_u32(dst + k), src + k);
            }
        }
        cp_commit();
    }

    int j = 0;
    for (long tile = blockIdx.x; tile < full_tiles; tile += G, j++) {
        const int cur = j & 1;

        // prefetch next tile into the other stage
        long nxt = tile + G;
        if (nxt < full_tiles) {
            const float4* src = (const float4*)(Fin + (size_t)nxt * TILE * 9);
            float4* dst = (float4*)sF[cur ^ 1];
            #pragma unroll
            for (int i = 0; i < 3; i++) {
                int k = tid + i * BS;
                if (k < NB4) cp_async16(smem_u32(dst + k), src + k);
            }
        }
        cp_commit();
        cp_wait1();           // current tile's group complete (1 newer outstanding)
        __syncthreads();

        float Fp[9], o1[9], o2[9], o3[9];
        #pragma unroll
        for (int k = 0; k < 9; k++) Fp[k] = sF[cur][tid * 9 + k];
        compute_point(Fp, o1, o2, o3);

        const size_t base9 = (size_t)tile * TILE * 9;
        const float4* s4 = (const float4*)sO;

        // region 0: PK1
        #pragma unroll
        for (int k = 0; k < 9; k++) sO[tid * 9 + k] = o1[k];
        __syncthreads();
        {
            float4* dst = (float4*)(out + base9);
            #pragma unroll
            for (int i = 0; i < 3; i++) {
                int k = tid + i * BS;
                if (k < NB4) dst[k] = s4[k];
            }
        }
        __syncthreads();

        // region 1: PK2
        #pragma unroll
        for (int k = 0; k < 9; k++) sO[tid * 9 + k] = o2[k];
        __syncthreads();
        {
            float4* dst = (float4*)(out + nn + base9);
            #pragma unroll
            for (int i = 0; i < 3; i++) {
                int k = tid + i * BS;
                if (k < NB4) dst[k] = s4[k];
            }
        }
        __syncthreads();

        // region 2: sigma
        #pragma unroll
        for (int k = 0; k < 9; k++) sO[tid * 9 + k] = o3[k];
        __syncthreads();
        {
            float4* dst = (float4*)(out + 2 * nn + base9);
            #pragma unroll
            for (int i = 0; i < 3; i++) {
                int k = tid + i * BS;
                if (k < NB4) dst[k] = s4[k];
            }
        }
        __syncthreads();
    }
}

__global__ void hyper_tail(const float* __restrict__ Fin,
                           float* __restrict__ out,
                           int n, int start)
{
    int idx = start + blockIdx.x * blockDim.x + threadIdx.x;
    if (idx >= n) return;
    float Fp[9], o1[9], o2[9], o3[9];
    #pragma unroll
    for (int k = 0; k < 9; k++) Fp[k] = Fin[(size_t)idx * 9 + k];
    compute_point(Fp, o1, o2, o3);
    size_t nn = (size_t)n * 9;
    #pragma unroll
    for (int k = 0; k < 9; k++) {
        out[(size_t)idx * 9 + k]          = o1[k];
        out[nn + (size_t)idx * 9 + k]     = o2[k];
        out[2 * nn + (size_t)idx * 9 + k] = o3[k];
    }
}

extern "C" void kernel_launch(void* const* d_in, const int* in_sizes, int n_in,
                              void* d_out, int out_size)
{
    const float* F = (const float*)d_in[0];
    float* out = (float*)d_out;
    int n = in_sizes[0] / 9;

    int full_tiles = n / TILE;
    int tail_start = full_tiles * TILE;
    int tail_cnt   = n - tail_start;

    if (full_tiles > 0) {
        int blocks = full_tiles < 888 ? full_tiles : 888;   // ~6 blocks/SM on 148 SMs
        hyper_main<<<blocks, BS>>>(F, out, full_tiles, (size_t)n * 9);
    }
    if (tail_cnt > 0) {
        int tb = (tail_cnt + 255) / 256;
        hyper_tail<<<tb, 256>>>(F, out, n, tail_start);
    }
}

// round 4
// speedup vs baseline: 1.1411x; 1.1411x over previous
#include <cuda_runtime.h>

// Hyperelasticity: closed-form Neo-Hookean stress.
// PK1 = MU*F + (LAM*lnJ - MU)*F^{-T};  PK2 = sym(F^{-1} PK1);  sig = sym(PK1 F^T)/J
//
// smem-staged, fully-coalesced float4 gmem traffic. BS=128 for finer
// per-SM block staggering (12 blocks/SM) to hide the load->barrier bubble.
#define MU  1.0f
#define LAM 1.0f
#define BS  128
#define NB4 ((BS * 9) / 4)   // 288 float4 per tile region

__device__ __forceinline__ void compute_point(const float* __restrict__ Fp,
                                              float* __restrict__ o1,
                                              float* __restrict__ o2,
                                              float* __restrict__ o3)
{
    float a = Fp[0], b = Fp[1], c = Fp[2];
    float d = Fp[3], e = Fp[4], f = Fp[5];
    float g = Fp[6], h = Fp[7], i = Fp[8];

    // cofactors: F^{-T} = C/J, F^{-1} = C^T/J
    float C00 = fmaf(e, i, -f * h);
    float C01 = fmaf(f, g, -d * i);
    float C02 = fmaf(d, h, -e * g);
    float C10 = fmaf(c, h, -b * i);
    float C11 = fmaf(a, i, -c * g);
    float C12 = fmaf(b, g, -a * h);
    float C20 = fmaf(b, f, -c * e);
    float C21 = fmaf(c, d, -a * f);
    float C22 = fmaf(a, e, -b * d);

    float J   = a * C00 + b * C01 + c * C02;
    float rJ  = __frcp_rn(J);
    float lnJ = __logf(J);

    float s = (LAM * lnJ - MU) * rJ;
    float P00 = fmaf(s, C00, MU * a);
    float P01 = fmaf(s, C01, MU * b);
    float P02 = fmaf(s, C02, MU * c);
    float P10 = fmaf(s, C10, MU * d);
    float P11 = fmaf(s, C11, MU * e);
    float P12 = fmaf(s, C12, MU * f);
    float P20 = fmaf(s, C20, MU * g);
    float P21 = fmaf(s, C21, MU * h);
    float P22 = fmaf(s, C22, MU * i);

    // Finv = C^T/J
    float I00 = C00 * rJ, I01 = C10 * rJ, I02 = C20 * rJ;
    float I10 = C01 * rJ, I11 = C11 * rJ, I12 = C21 * rJ;
    float I20 = C02 * rJ, I21 = C12 * rJ, I22 = C22 * rJ;

    float M00 = I00*P00 + I01*P10 + I02*P20;
    float M01 = I00*P01 + I01*P11 + I02*P21;
    float M02 = I00*P02 + I01*P12 + I02*P22;
    float M10 = I10*P00 + I11*P10 + I12*P20;
    float M11 = I10*P01 + I11*P11 + I12*P21;
    float M12 = I10*P02 + I11*P12 + I12*P22;
    float M20 = I20*P00 + I21*P10 + I22*P20;
    float M21 = I20*P01 + I21*P11 + I22*P21;
    float M22 = I20*P02 + I21*P12 + I22*P22;

    float S01 = 0.5f * (M01 + M10);
    float S02 = 0.5f * (M02 + M20);
    float S12 = 0.5f * (M12 + M21);

    float T00 = P00*a + P01*b + P02*c;
    float T01 = P00*d + P01*e + P02*f;
    float T02 = P00*g + P01*h + P02*i;
    float T10 = P10*a + P11*b + P12*c;
    float T11 = P10*d + P11*e + P12*f;
    float T12 = P10*g + P11*h + P12*i;
    float T20 = P20*a + P21*b + P22*c;
    float T21 = P20*d + P21*e + P22*f;
    float T22 = P20*g + P21*h + P22*i;

    o1[0] = P00; o1[1] = P01; o1[2] = P02;
    o1[3] = P10; o1[4] = P11; o1[5] = P12;
    o1[6] = P20; o1[7] = P21; o1[8] = P22;

    o2[0] = M00; o2[1] = S01; o2[2] = S02;
    o2[3] = S01; o2[4] = M11; o2[5] = S12;
    o2[6] = S02; o2[7] = S12; o2[8] = M22;

    float G01 = 0.5f * (T01 + T10) * rJ;
    float G02 = 0.5f * (T02 + T20) * rJ;
    float G12 = 0.5f * (T12 + T21) * rJ;
    o3[0] = T00 * rJ; o3[1] = G01;      o3[2] = G02;
    o3[3] = G01;      o3[4] = T11 * rJ; o3[5] = G12;
    o3[6] = G02;      o3[7] = G12;      o3[8] = T22 * rJ;
}

__global__ __launch_bounds__(BS)
void hyper_kernel(const float* __restrict__ Fin,
                  float* __restrict__ out,
                  int n)
{
    __shared__ __align__(16) float sF[BS * 9];       // staged input  (4.5 KB)
    __shared__ __align__(16) float sO[3][BS * 9];    // staged output (13.5 KB)

    const int tid  = threadIdx.x;
    const int base = blockIdx.x * BS;
    const size_t nn = (size_t)n * 9;

    if (base + BS <= n) {
        // ---- full block: fully vectorized path ----
        const float4* src = (const float4*)(Fin + (size_t)base * 9);
        float4* sF4 = (float4*)sF;
        #pragma unroll
        for (int i = 0; i < 3; i++) {
            int k = tid + i * BS;
            if (k < NB4) sF4[k] = src[k];
        }
        __syncthreads();

        float Fp[9], o1[9], o2[9], o3[9];
        #pragma unroll
        for (int k = 0; k < 9; k++) Fp[k] = sF[tid * 9 + k];

        compute_point(Fp, o1, o2, o3);

        #pragma unroll
        for (int k = 0; k < 9; k++) {
            sO[0][tid * 9 + k] = o1[k];
            sO[1][tid * 9 + k] = o2[k];
            sO[2][tid * 9 + k] = o3[k];
        }
        __syncthreads();

        #pragma unroll
        for (int r = 0; r < 3; r++) {
            float4* dst = (float4*)(out + r * nn + (size_t)base * 9);
            const float4* s4 = (const float4*)sO[r];
            #pragma unroll
            for (int i = 0; i < 3; i++) {
                int k = tid + i * BS;
                if (k < NB4) dst[k] = s4[k];
            }
        }
    } else {
        // ---- tail block: scalar guarded path ----
        int idx = base + tid;
        if (idx < n) {
            float Fp[9], o1[9], o2[9], o3[9];
            #pragma unroll
            for (int k = 0; k < 9; k++) Fp[k] = Fin[(size_t)idx * 9 + k];
            compute_point(Fp, o1, o2, o3);
            #pragma unroll
            for (int k = 0; k < 9; k++) {
                out[(size_t)idx * 9 + k]          = o1[k];
                out[nn + (size_t)idx * 9 + k]     = o2[k];
                out[2 * nn + (size_t)idx * 9 + k] = o3[k];
            }
        }
    }
}

extern "C" void kernel_launch(void* const* d_in, const int* in_sizes, int n_in,
                              void* d_out, int out_size)
{
    const float* F = (const float*)d_in[0];
    float* out = (float*)d_out;
    int n = in_sizes[0] / 9;

    int blocks = (n + BS - 1) / BS;
    hyper_kernel<<<blocks, BS>>>(F, out, n);
}